// round 9
// baseline (speedup 1.0000x reference)
#include <cuda_runtime.h>

#define N_NODES 100000
#define N_EDGES 1600000
#define D 128
#define BM 128
#define MAXDEG 64

// Static device scratch (no allocations allowed)
__device__ float g_hn[(size_t)N_NODES * D];                 // 51.2 MB
__device__ int   g_esrc[(size_t)N_NODES * MAXDEG];          // 25.6 MB padded CSR
__device__ int   g_cur[N_NODES];                            // per-node degree/cursor

// ---------------------------------------------------------------------------
// Kernel 1: hn[n,:] = (features[n,:] @ W^T + b) * norm[n]
// 512 threads, 128x128 block, 4 rows x 8 cols per thread (col groups tx*4 and
// 64+tx*4 -> conflict-free w-frag LDS.128). Scalar FFMA inner loop (the
// packed f32x2 experiment regressed ~20us; reverted).
// ---------------------------------------------------------------------------
__global__ void __launch_bounds__(512, 1) gemm_norm_kernel(
    const float* __restrict__ A,
    const float* __restrict__ norm,
    const float* __restrict__ W,
    const float* __restrict__ b)
{
    extern __shared__ float smem[];
    float* Ws = smem;            // [k:128][j:128] swizzled; Ws(k,j) = W[j][k]
    float* As = smem + D * D;    // [k:128][r:128] swizzled; As(k,r) = A[row0+r][k]

    const int tid = threadIdx.x;
    const int tx  = tid & 15;    // col groups: tx*4 and 64+tx*4
    const int ty  = tid >> 4;    // 0..31 -> rows ty*4 .. ty*4+3
    const int row0 = blockIdx.x * BM;

    // --- Stage W (k-major, swizzled stores)
    for (int idx = tid; idx < D * (D / 4); idx += 512) {
        int j  = idx >> 5;            // output col 0..127
        int kc = idx & 31;            // float4 index along k
        float4 v = reinterpret_cast<const float4*>(W)[idx];
        int m = (kc & 7) << 2;
        Ws[(4 * kc + 0) * D + (j ^ m)] = v.x;
        Ws[(4 * kc + 1) * D + (j ^ m)] = v.y;
        Ws[(4 * kc + 2) * D + (j ^ m)] = v.z;
        Ws[(4 * kc + 3) * D + (j ^ m)] = v.w;
    }
    // --- Stage A tile (k-major, swizzled), zero-pad tail rows
    for (int idx = tid; idx < BM * (D / 4); idx += 512) {
        int r  = idx >> 5;
        int kc = idx & 31;
        int grow = row0 + r;
        float4 v = make_float4(0.f, 0.f, 0.f, 0.f);
        if (grow < N_NODES)
            v = reinterpret_cast<const float4*>(A)[(size_t)grow * 32 + kc];
        int m = (kc & 7) << 2;
        As[(4 * kc + 0) * D + (r ^ m)] = v.x;
        As[(4 * kc + 1) * D + (r ^ m)] = v.y;
        As[(4 * kc + 2) * D + (r ^ m)] = v.z;
        As[(4 * kc + 3) * D + (r ^ m)] = v.w;
    }
    __syncthreads();

    float acc[4][8];
#pragma unroll
    for (int r = 0; r < 4; r++)
#pragma unroll
        for (int c = 0; c < 8; c++) acc[r][c] = 0.f;

    const int c0 = tx * 4;
    const int c1 = 64 + tx * 4;
    const int r0 = ty * 4;

#pragma unroll 2
    for (int t = 0; t < 32; t++) {          // 4 k's per t; swizzle mask const
        int m = (t & 7) << 2;
        const float* wp = Ws + (4 * t) * D;
        const float* ap = As + (4 * t) * D;
        int c0s = c0 ^ m, c1s = c1 ^ m, r0s = r0 ^ m;
#pragma unroll
        for (int i = 0; i < 4; i++) {
            float4 w0 = *reinterpret_cast<const float4*>(wp + i * D + c0s);
            float4 w1 = *reinterpret_cast<const float4*>(wp + i * D + c1s);
            float4 a  = *reinterpret_cast<const float4*>(ap + i * D + r0s);
            float av[4] = {a.x, a.y, a.z, a.w};
            float wv[8] = {w0.x, w0.y, w0.z, w0.w, w1.x, w1.y, w1.z, w1.w};
#pragma unroll
            for (int r = 0; r < 4; r++)
#pragma unroll
                for (int c = 0; c < 8; c++)
                    acc[r][c] += av[r] * wv[c];
        }
    }

    // --- Epilogue: hn = (acc + b) * norm
    float4 bb0 = reinterpret_cast<const float4*>(b)[tx];       // cols tx*4..+3
    float4 bb1 = reinterpret_cast<const float4*>(b)[16 + tx];  // cols 64+tx*4..
#pragma unroll
    for (int i = 0; i < 4; i++) {
        int grow = row0 + r0 + i;
        if (grow < N_NODES) {
            float nr = norm[grow];
            float4 o0, o1;
            o0.x = (acc[i][0] + bb0.x) * nr;
            o0.y = (acc[i][1] + bb0.y) * nr;
            o0.z = (acc[i][2] + bb0.z) * nr;
            o0.w = (acc[i][3] + bb0.w) * nr;
            o1.x = (acc[i][4] + bb1.x) * nr;
            o1.y = (acc[i][5] + bb1.y) * nr;
            o1.z = (acc[i][6] + bb1.z) * nr;
            o1.w = (acc[i][7] + bb1.w) * nr;
            float4* hp = reinterpret_cast<float4*>(g_hn) + (size_t)grow * 32;
            hp[tx]      = o0;
            hp[16 + tx] = o1;
        }
    }
}

// ---------------------------------------------------------------------------
// Kernel 2: bucket edge sources by destination (padded CSR build).
// 4 edges per thread via int4 loads (latency-bound kernel: issue was 6%).
// ---------------------------------------------------------------------------
__global__ void __launch_bounds__(256) reorder_kernel(
    const int4* __restrict__ src4,
    const int4* __restrict__ dst4)
{
    int t = blockIdx.x * 256 + threadIdx.x;
    if (t >= N_EDGES / 4) return;
    int4 s = __ldg(&src4[t]);
    int4 d = __ldg(&dst4[t]);
    int p;
    p = atomicAdd(&g_cur[d.x], 1); if (p < MAXDEG) g_esrc[(size_t)d.x * MAXDEG + p] = s.x;
    p = atomicAdd(&g_cur[d.y], 1); if (p < MAXDEG) g_esrc[(size_t)d.y * MAXDEG + p] = s.y;
    p = atomicAdd(&g_cur[d.z], 1); if (p < MAXDEG) g_esrc[(size_t)d.z * MAXDEG + p] = s.z;
    p = atomicAdd(&g_cur[d.w], 1); if (p < MAXDEG) g_esrc[(size_t)d.w * MAXDEG + p] = s.w;
}

// ---------------------------------------------------------------------------
// Kernel 3: pull-mode aggregation. One warp per dst node; 8 gathers in
// flight per warp (MLP=8); register acc; fused *norm[dst] + relu; writes
// out exactly once (covers deg==0).
// ---------------------------------------------------------------------------
__global__ void __launch_bounds__(256) agg_kernel(
    float* __restrict__ out, const float* __restrict__ norm)
{
    int n = blockIdx.x * 8 + (threadIdx.x >> 5);
    if (n >= N_NODES) return;
    int lane = threadIdx.x & 31;
    int deg = g_cur[n];
    if (deg > MAXDEG) deg = MAXDEG;   // safety (never expected)

    const float4* hn4 = reinterpret_cast<const float4*>(g_hn);
    float4 acc = make_float4(0.f, 0.f, 0.f, 0.f);
    const int* bucket = g_esrc + (size_t)n * MAXDEG;

    for (int c = 0; c < deg; c += 32) {
        int idx = 0;
        if (c + lane < deg) idx = bucket[c + lane];
        int m = min(32, deg - c);
        int j = 0;
        for (; j + 8 <= m; j += 8) {
            float4 v[8];
#pragma unroll
            for (int q = 0; q < 8; q++) {
                int s = __shfl_sync(0xffffffffu, idx, j + q);
                v[q] = __ldg(&hn4[(size_t)s * 32 + lane]);
            }
#pragma unroll
            for (int q = 0; q < 8; q++) {
                acc.x += v[q].x; acc.y += v[q].y;
                acc.z += v[q].z; acc.w += v[q].w;
            }
        }
        for (; j + 4 <= m; j += 4) {
            float4 v[4];
#pragma unroll
            for (int q = 0; q < 4; q++) {
                int s = __shfl_sync(0xffffffffu, idx, j + q);
                v[q] = __ldg(&hn4[(size_t)s * 32 + lane]);
            }
#pragma unroll
            for (int q = 0; q < 4; q++) {
                acc.x += v[q].x; acc.y += v[q].y;
                acc.z += v[q].z; acc.w += v[q].w;
            }
        }
        for (; j < m; j++) {
            int s = __shfl_sync(0xffffffffu, idx, j);
            float4 v = __ldg(&hn4[(size_t)s * 32 + lane]);
            acc.x += v.x; acc.y += v.y; acc.z += v.z; acc.w += v.w;
        }
    }

    float nr = norm[n];
    float4 o;
    o.x = fmaxf(acc.x * nr, 0.f);
    o.y = fmaxf(acc.y * nr, 0.f);
    o.z = fmaxf(acc.z * nr, 0.f);
    o.w = fmaxf(acc.w * nr, 0.f);
    reinterpret_cast<float4*>(out)[(size_t)n * 32 + lane] = o;
}

// ---------------------------------------------------------------------------
extern "C" void kernel_launch(void* const* d_in, const int* in_sizes, int n_in,
                              void* d_out, int out_size)
{
    const float* features = (const float*)d_in[0];
    const float* norm     = (const float*)d_in[1];
    const float* W        = (const float*)d_in[2];
    const float* b        = (const float*)d_in[3];
    const int*   src      = (const int*)d_in[4];
    const int*   dst      = (const int*)d_in[5];
    float* out = (float*)d_out;

    const int smem_bytes = 2 * D * D * sizeof(float); // 128 KB
    cudaFuncSetAttribute(gemm_norm_kernel,
                         cudaFuncAttributeMaxDynamicSharedMemorySize, smem_bytes);

    // One-time side-stream/event setup (infra, not device memory)
    static cudaStream_t s_side = nullptr;
    static cudaEvent_t  s_fork = nullptr, s_join = nullptr;
    if (!s_side) {
        cudaStreamCreateWithFlags(&s_side, cudaStreamNonBlocking);
        cudaEventCreateWithFlags(&s_fork, cudaEventDisableTiming);
        cudaEventCreateWithFlags(&s_join, cudaEventDisableTiming);
    }

    void* cur_ptr = nullptr;
    cudaGetSymbolAddress(&cur_ptr, g_cur);

    // Fork: CSR build (memset + reorder) runs concurrently with the GEMM.
    cudaEventRecord(s_fork, 0);
    cudaStreamWaitEvent(s_side, s_fork, 0);
    cudaMemsetAsync(cur_ptr, 0, N_NODES * sizeof(int), s_side);
    reorder_kernel<<<(N_EDGES / 4 + 255) / 256, 256, 0, s_side>>>(
        (const int4*)src, (const int4*)dst);
    cudaEventRecord(s_join, s_side);

    int gemm_blocks = (N_NODES + BM - 1) / BM; // 782
    gemm_norm_kernel<<<gemm_blocks, 512, smem_bytes>>>(features, norm, W, b);

    // Join: agg needs both hn and the CSR.
    cudaStreamWaitEvent(0, s_join, 0);
    agg_kernel<<<(N_NODES + 7) / 8, 256>>>(out, norm);
}

// round 10
// speedup vs baseline: 1.1764x; 1.1764x over previous
#include <cuda_runtime.h>
#include <cuda_fp16.h>

#define N_NODES 100000
#define N_EDGES 1600000
#define D 128
#define BM 128
#define MAXDEG 64

// Static device scratch (no allocations allowed)
__device__ __half g_hn[(size_t)N_NODES * D];                // 25.6 MB (fp16!)
__device__ int    g_esrc[(size_t)N_NODES * MAXDEG];         // 25.6 MB padded CSR
__device__ int    g_cur[N_NODES];                           // per-node degree/cursor

// ---- packed fp32x2 helpers (proven ~19us GEMM win in R7-vs-R9 A/B) --------
__device__ __forceinline__ unsigned long long pack2(float x, float y) {
    unsigned long long r;
    asm("mov.b64 %0, {%1, %2};" : "=l"(r) : "f"(x), "f"(y));
    return r;
}
__device__ __forceinline__ void unpack2(unsigned long long v, float& x, float& y) {
    asm("mov.b64 {%0, %1}, %2;" : "=f"(x), "=f"(y) : "l"(v));
}
__device__ __forceinline__ void ffma2(unsigned long long& d,
                                      unsigned long long a,
                                      unsigned long long b) {
    asm("fma.rn.f32x2 %0, %1, %2, %0;" : "+l"(d) : "l"(a), "l"(b));
}

// ---------------------------------------------------------------------------
// Kernel 1: hn[n,:] = fp16( (features[n,:] @ W^T + b) * norm[n] )
// 512 threads, 128x128 block, 4 rows x 8 cols per thread, fma.rn.f32x2 inner
// loop (w pairs straight out of LDS.128 as ulonglong2).
// ---------------------------------------------------------------------------
__global__ void __launch_bounds__(512, 1) gemm_norm_kernel(
    const float* __restrict__ A,
    const float* __restrict__ norm,
    const float* __restrict__ W,
    const float* __restrict__ b)
{
    extern __shared__ float smem[];
    float* Ws = smem;            // [k:128][j:128] swizzled; Ws(k,j) = W[j][k]
    float* As = smem + D * D;    // [k:128][r:128] swizzled; As(k,r) = A[row0+r][k]

    const int tid = threadIdx.x;
    const int tx  = tid & 15;    // col groups: tx*4 and 64+tx*4
    const int ty  = tid >> 4;    // 0..31 -> rows ty*4 .. ty*4+3
    const int row0 = blockIdx.x * BM;

    // --- Stage W (k-major, swizzled stores)
    for (int idx = tid; idx < D * (D / 4); idx += 512) {
        int j  = idx >> 5;            // output col 0..127
        int kc = idx & 31;            // float4 index along k
        float4 v = reinterpret_cast<const float4*>(W)[idx];
        int m = (kc & 7) << 2;
        Ws[(4 * kc + 0) * D + (j ^ m)] = v.x;
        Ws[(4 * kc + 1) * D + (j ^ m)] = v.y;
        Ws[(4 * kc + 2) * D + (j ^ m)] = v.z;
        Ws[(4 * kc + 3) * D + (j ^ m)] = v.w;
    }
    // --- Stage A tile (k-major, swizzled), zero-pad tail rows
    for (int idx = tid; idx < BM * (D / 4); idx += 512) {
        int r  = idx >> 5;
        int kc = idx & 31;
        int grow = row0 + r;
        float4 v = make_float4(0.f, 0.f, 0.f, 0.f);
        if (grow < N_NODES)
            v = reinterpret_cast<const float4*>(A)[(size_t)grow * 32 + kc];
        int m = (kc & 7) << 2;
        As[(4 * kc + 0) * D + (r ^ m)] = v.x;
        As[(4 * kc + 1) * D + (r ^ m)] = v.y;
        As[(4 * kc + 2) * D + (r ^ m)] = v.z;
        As[(4 * kc + 3) * D + (r ^ m)] = v.w;
    }
    __syncthreads();

    // acc2[r][p]: packed pair p of row r. p=0,1 -> cols c0..c0+3; p=2,3 -> c1..
    unsigned long long acc2[4][4];
#pragma unroll
    for (int r = 0; r < 4; r++)
#pragma unroll
        for (int p = 0; p < 4; p++) acc2[r][p] = 0ULL;

    const int c0 = tx * 4;
    const int c1 = 64 + tx * 4;
    const int r0 = ty * 4;

#pragma unroll 2
    for (int t = 0; t < 32; t++) {          // 4 k's per t; swizzle mask const
        int m = (t & 7) << 2;
        const float* wp = Ws + (4 * t) * D;
        const float* ap = As + (4 * t) * D;
        int c0s = c0 ^ m, c1s = c1 ^ m, r0s = r0 ^ m;
#pragma unroll
        for (int i = 0; i < 4; i++) {
            ulonglong2 w0 = *reinterpret_cast<const ulonglong2*>(wp + i * D + c0s);
            ulonglong2 w1 = *reinterpret_cast<const ulonglong2*>(wp + i * D + c1s);
            float4 a      = *reinterpret_cast<const float4*>(ap + i * D + r0s);
            unsigned long long av[4] = {
                pack2(a.x, a.x), pack2(a.y, a.y), pack2(a.z, a.z), pack2(a.w, a.w)
            };
#pragma unroll
            for (int r = 0; r < 4; r++) {
                ffma2(acc2[r][0], av[r], w0.x);
                ffma2(acc2[r][1], av[r], w0.y);
                ffma2(acc2[r][2], av[r], w1.x);
                ffma2(acc2[r][3], av[r], w1.y);
            }
        }
    }

    // --- Epilogue: hn = fp16((acc + b) * norm)
    float4 bb0 = reinterpret_cast<const float4*>(b)[tx];       // cols tx*4..+3
    float4 bb1 = reinterpret_cast<const float4*>(b)[16 + tx];  // cols 64+tx*4..
#pragma unroll
    for (int i = 0; i < 4; i++) {
        int grow = row0 + r0 + i;
        if (grow < N_NODES) {
            float nr = norm[grow];
            float a0, a1, a2, a3, a4, a5, a6, a7;
            unpack2(acc2[i][0], a0, a1);
            unpack2(acc2[i][1], a2, a3);
            unpack2(acc2[i][2], a4, a5);
            unpack2(acc2[i][3], a6, a7);
            __half2 h0 = __floats2half2_rn((a0 + bb0.x) * nr, (a1 + bb0.y) * nr);
            __half2 h1 = __floats2half2_rn((a2 + bb0.z) * nr, (a3 + bb0.w) * nr);
            __half2 h2 = __floats2half2_rn((a4 + bb1.x) * nr, (a5 + bb1.y) * nr);
            __half2 h3 = __floats2half2_rn((a6 + bb1.z) * nr, (a7 + bb1.w) * nr);
            uint2 u0, u1;
            u0.x = reinterpret_cast<unsigned&>(h0);
            u0.y = reinterpret_cast<unsigned&>(h1);
            u1.x = reinterpret_cast<unsigned&>(h2);
            u1.y = reinterpret_cast<unsigned&>(h3);
            // row = 128 halves = 32 uint2; group A at uint2 idx tx, B at 16+tx
            uint2* hp = reinterpret_cast<uint2*>(g_hn + (size_t)grow * D);
            hp[tx]      = u0;
            hp[16 + tx] = u1;
        }
    }
}

// ---------------------------------------------------------------------------
// Kernel 2: bucket edge sources by destination (padded CSR build).
// 4 edges per thread via int4 loads.
// ---------------------------------------------------------------------------
__global__ void __launch_bounds__(256) reorder_kernel(
    const int4* __restrict__ src4,
    const int4* __restrict__ dst4)
{
    int t = blockIdx.x * 256 + threadIdx.x;
    if (t >= N_EDGES / 4) return;
    int4 s = __ldg(&src4[t]);
    int4 d = __ldg(&dst4[t]);
    int p;
    p = atomicAdd(&g_cur[d.x], 1); if (p < MAXDEG) g_esrc[(size_t)d.x * MAXDEG + p] = s.x;
    p = atomicAdd(&g_cur[d.y], 1); if (p < MAXDEG) g_esrc[(size_t)d.y * MAXDEG + p] = s.y;
    p = atomicAdd(&g_cur[d.z], 1); if (p < MAXDEG) g_esrc[(size_t)d.z * MAXDEG + p] = s.z;
    p = atomicAdd(&g_cur[d.w], 1); if (p < MAXDEG) g_esrc[(size_t)d.w * MAXDEG + p] = s.w;
}

// ---------------------------------------------------------------------------
// Kernel 3: pull-mode aggregation over fp16 hn. One warp per dst node; lane
// covers cols 4*lane..4*lane+3 via one 8B uint2 (4 halves); fp32 register acc;
// fused *norm[dst] + relu; writes out exactly once (covers deg==0).
// ---------------------------------------------------------------------------
__global__ void __launch_bounds__(256) agg_kernel(
    float* __restrict__ out, const float* __restrict__ norm)
{
    int n = blockIdx.x * 8 + (threadIdx.x >> 5);
    if (n >= N_NODES) return;
    int lane = threadIdx.x & 31;
    int deg = g_cur[n];
    if (deg > MAXDEG) deg = MAXDEG;   // safety (never expected)

    const uint2* hn2 = reinterpret_cast<const uint2*>(g_hn);  // 32 uint2 per row
    float4 acc = make_float4(0.f, 0.f, 0.f, 0.f);
    const int* bucket = g_esrc + (size_t)n * MAXDEG;

    for (int c = 0; c < deg; c += 32) {
        int idx = 0;
        if (c + lane < deg) idx = bucket[c + lane];
        int m = min(32, deg - c);
        int j = 0;
        for (; j + 4 <= m; j += 4) {
            uint2 v[4];
#pragma unroll
            for (int q = 0; q < 4; q++) {
                int s = __shfl_sync(0xffffffffu, idx, j + q);
                v[q] = __ldg(&hn2[(size_t)s * 32 + lane]);
            }
#pragma unroll
            for (int q = 0; q < 4; q++) {
                float2 f01 = __half22float2(reinterpret_cast<__half2&>(v[q].x));
                float2 f23 = __half22float2(reinterpret_cast<__half2&>(v[q].y));
                acc.x += f01.x; acc.y += f01.y;
                acc.z += f23.x; acc.w += f23.y;
            }
        }
        for (; j < m; j++) {
            int s = __shfl_sync(0xffffffffu, idx, j);
            uint2 v = __ldg(&hn2[(size_t)s * 32 + lane]);
            float2 f01 = __half22float2(reinterpret_cast<__half2&>(v.x));
            float2 f23 = __half22float2(reinterpret_cast<__half2&>(v.y));
            acc.x += f01.x; acc.y += f01.y;
            acc.z += f23.x; acc.w += f23.y;
        }
    }

    float nr = norm[n];
    float4 o;
    o.x = fmaxf(acc.x * nr, 0.f);
    o.y = fmaxf(acc.y * nr, 0.f);
    o.z = fmaxf(acc.z * nr, 0.f);
    o.w = fmaxf(acc.w * nr, 0.f);
    reinterpret_cast<float4*>(out)[(size_t)n * 32 + lane] = o;
}

// ---------------------------------------------------------------------------
extern "C" void kernel_launch(void* const* d_in, const int* in_sizes, int n_in,
                              void* d_out, int out_size)
{
    const float* features = (const float*)d_in[0];
    const float* norm     = (const float*)d_in[1];
    const float* W        = (const float*)d_in[2];
    const float* b        = (const float*)d_in[3];
    const int*   src      = (const int*)d_in[4];
    const int*   dst      = (const int*)d_in[5];
    float* out = (float*)d_out;

    const int smem_bytes = 2 * D * D * sizeof(float); // 128 KB
    cudaFuncSetAttribute(gemm_norm_kernel,
                         cudaFuncAttributeMaxDynamicSharedMemorySize, smem_bytes);

    // One-time side-stream/event setup (infra, not device memory)
    static cudaStream_t s_side = nullptr;
    static cudaEvent_t  s_fork = nullptr, s_join = nullptr;
    if (!s_side) {
        cudaStreamCreateWithFlags(&s_side, cudaStreamNonBlocking);
        cudaEventCreateWithFlags(&s_fork, cudaEventDisableTiming);
        cudaEventCreateWithFlags(&s_join, cudaEventDisableTiming);
    }

    void* cur_ptr = nullptr;
    cudaGetSymbolAddress(&cur_ptr, g_cur);

    // Fork: CSR build (memset + reorder) runs concurrently with the GEMM.
    cudaEventRecord(s_fork, 0);
    cudaStreamWaitEvent(s_side, s_fork, 0);
    cudaMemsetAsync(cur_ptr, 0, N_NODES * sizeof(int), s_side);
    reorder_kernel<<<(N_EDGES / 4 + 255) / 256, 256, 0, s_side>>>(
        (const int4*)src, (const int4*)dst);
    cudaEventRecord(s_join, s_side);

    int gemm_blocks = (N_NODES + BM - 1) / BM; // 782
    gemm_norm_kernel<<<gemm_blocks, 512, smem_bytes>>>(features, norm, W, b);

    // Join: agg needs both hn and the CSR.
    cudaStreamWaitEvent(0, s_join, 0);
    agg_kernel<<<(N_NODES + 7) / 8, 256>>>(out, norm);
}